// round 1
// baseline (speedup 1.0000x reference)
#include <cuda_runtime.h>
#include <cuda_bf16.h>

// Problem constants
#define B_   128
#define C_   64
#define H_   32
#define W_   32
#define O_   64
#define OH_  30
#define OW_  30
#define KS   3
#define NPOS (OH_ * OW_)      // 900
#define BKC  8                // channels per K-chunk
#define BK   (BKC * KS * KS)  // 72 p-values per chunk
#define PAD  1                // smem row padding -> stride 73 (73%32=9, conflict-free)

// out[b,o,i,j] = sum_{c,kh,kw} x[b,c,i+kh,j+kw] * weight[c,o,i,j,kh,kw] + bias[o,i,j]
// One block per spatial position (i,j): GEMM M=128(b) x N=64(o), K=576.
__global__ __launch_bounds__(256, 2)
void lc_kernel(const float* __restrict__ x, const float* __restrict__ wt,
               const float* __restrict__ bias, float* __restrict__ out) {
    const int pos = blockIdx.x;          // i*30 + j
    const int oi  = pos / OW_;
    const int oj  = pos % OW_;
    const int tid = threadIdx.x;

    __shared__ float As[B_][BK + PAD];   // [b][p]  128*73*4 = 37376 B
    __shared__ float Ws[O_][BK + PAD];   // [o][p]   64*73*4 = 18688 B

    const int n0 = (tid & 15) * 4;       // o-tile base (4 wide)
    const int m0 = (tid >> 4) * 8;       // b-tile base (8 tall)

    float acc[8][4];
    #pragma unroll
    for (int mm = 0; mm < 8; mm++)
        #pragma unroll
        for (int nn = 0; nn < 4; nn++) acc[mm][nn] = 0.f;

    for (int c0 = 0; c0 < C_; c0 += BKC) {
        // ---- Stage weight chunk: Ws[o][p], p = cc*9 + kh*3 + kw.
        // K-fastest thread mapping: consecutive threads read the 9 contiguous
        // floats of weight[(c0+cc)][o][oi][oj][0..8] -> decent coalescing.
        #pragma unroll
        for (int t = 0; t < (BK * O_) / 256; t++) {       // 18 iters
            int idx = tid + t * 256;
            int p = idx % BK;
            int o = idx / BK;
            int cc = p / 9, r = p % 9;
            Ws[o][p] = wt[(((c0 + cc) * O_ + o) * NPOS + pos) * 9 + r];
        }
        // ---- Stage patch chunk: As[b][p] = x[b][c0+cc][oi+kh][oj+kw].
        // Consecutive threads read consecutive p -> 3-float contiguous runs in x
        // (heavily L2-resident: x is 33.5 MB total, reused 9x across positions).
        #pragma unroll
        for (int t = 0; t < (BK * B_) / 256; t++) {       // 36 iters
            int idx = tid + t * 256;
            int p = idx % BK;
            int b = idx / BK;
            int cc = p / 9, r = p % 9;
            int kh = r / 3, kw = r % 3;
            As[b][p] = x[((b * C_ + (c0 + cc)) * H_ + (oi + kh)) * W_ + (oj + kw)];
        }
        __syncthreads();

        // ---- 128x64 outer-product accumulation over this K-chunk
        #pragma unroll 8
        for (int p = 0; p < BK; p++) {
            float a[8], w[4];
            #pragma unroll
            for (int mm = 0; mm < 8; mm++) a[mm] = As[m0 + mm][p];
            #pragma unroll
            for (int nn = 0; nn < 4; nn++) w[nn] = Ws[n0 + nn][p];
            #pragma unroll
            for (int mm = 0; mm < 8; mm++)
                #pragma unroll
                for (int nn = 0; nn < 4; nn++)
                    acc[mm][nn] += a[mm] * w[nn];
        }
        __syncthreads();
    }

    // ---- Epilogue: add bias, write out[b][o][pos] (pos is the contiguous axis,
    // so per-position blocks inherently write 4B-strided; rely on L2 merge of
    // adjacent-pos blocks for writeback).
    #pragma unroll
    for (int nn = 0; nn < 4; nn++) {
        float bv = bias[(n0 + nn) * NPOS + pos];
        #pragma unroll
        for (int mm = 0; mm < 8; mm++) {
            int b = m0 + mm;
            int o = n0 + nn;
            out[(b * O_ + o) * NPOS + pos] = acc[mm][nn] + bv;
        }
    }
}

extern "C" void kernel_launch(void* const* d_in, const int* in_sizes, int n_in,
                              void* d_out, int out_size) {
    const float* x    = (const float*)d_in[0];   // [128,64,32,32]
    const float* wt   = (const float*)d_in[1];   // [64,64,30,30,3,3]
    const float* bias = (const float*)d_in[2];   // [64,30,30]
    float* out = (float*)d_out;                  // [128,64,30,30]
    lc_kernel<<<NPOS, 256>>>(x, wt, bias, out);
}

// round 4
// speedup vs baseline: 3.4591x; 3.4591x over previous
#include <cuda_runtime.h>
#include <cuda_bf16.h>
#include <cstdint>

// ============================================================
// LocallyConnectedLayer: out[b,o,i,j] = sum_{c,kh,kw} x[b,c,i+kh,j+kw]
//                        * weight[c,o,i,j,kh,kw] + bias[o,i,j]
// B=128, C=64, O=64, H=W=32, OH=OW=30, K=3.
// 900 independent GEMMs M=128,N=64,K=576.
// tcgen05 is NOT compilable for this harness (PTX target sm_103 non-'a'),
// so use mma.sync.m16n8k16.bf16 (HMMA) with 3-product hi/lo bf16 split.
// ============================================================

#define NPOS 900
#define PW   8100      // NPOS*9

// ---- scratch (__device__ globals; allocation APIs are forbidden) ----
__device__ __align__(16) __nv_bfloat16 g_Whi[(size_t)PW * 64 * 64];   // [P][o][c]
__device__ __align__(16) __nv_bfloat16 g_Wlo[(size_t)PW * 64 * 64];
__device__ __align__(16) __nv_bfloat16 g_Xhi[(size_t)1024 * 8192];    // [s][b*64+c]
__device__ __align__(16) __nv_bfloat16 g_Xlo[(size_t)1024 * 8192];

// ---- helpers ----
__device__ __forceinline__ uint32_t smem_to_u32(const void* p) {
    uint32_t a;
    asm("{ .reg .u64 t; cvta.to.shared.u64 t, %1; cvt.u32.u64 %0, t; }" : "=r"(a) : "l"(p));
    return a;
}
__device__ __forceinline__ void cp16(uint32_t dst, const void* src) {
    asm volatile("cp.async.cg.shared.global [%0], [%1], 16;" :: "r"(dst), "l"(src) : "memory");
}
#define CP_COMMIT()  asm volatile("cp.async.commit_group;" ::: "memory")
#define CP_WAIT(n)   asm volatile("cp.async.wait_group %0;" :: "n"(n) : "memory")

__device__ __forceinline__ void ldsm_x4(uint32_t a[4], uint32_t addr) {
    asm volatile("ldmatrix.sync.aligned.m8n8.x4.shared.b16 {%0,%1,%2,%3}, [%4];"
        : "=r"(a[0]), "=r"(a[1]), "=r"(a[2]), "=r"(a[3]) : "r"(addr));
}
__device__ __forceinline__ void mma_bf16(float c[4], const uint32_t a[4], const uint32_t b[2]) {
    asm volatile(
        "mma.sync.aligned.m16n8k16.row.col.f32.bf16.bf16.f32 "
        "{%0,%1,%2,%3},{%4,%5,%6,%7},{%8,%9},{%0,%1,%2,%3};"
        : "+f"(c[0]), "+f"(c[1]), "+f"(c[2]), "+f"(c[3])
        : "r"(a[0]), "r"(a[1]), "r"(a[2]), "r"(a[3]), "r"(b[0]), "r"(b[1]));
}
#define SWZ(off) ((off) ^ (((off) >> 3) & 0x70))

// ============================================================
// Prepass 1: weight [c][o][P] fp32 -> Whi/Wlo [P][o][c] bf16
// ============================================================
__global__ __launch_bounds__(256) void prep_w(const float* __restrict__ wt) {
    __shared__ float t[32][33];
    const int P0 = blockIdx.x * 32;
    const int o  = blockIdx.y;
    const int c0 = blockIdx.z * 32;
    const int tx = threadIdx.x, ty = threadIdx.y;  // 32 x 8
    #pragma unroll
    for (int i = 0; i < 4; i++) {
        int cl = ty + i * 8;
        int P  = P0 + tx;
        t[cl][tx] = (P < PW) ? wt[((size_t)(c0 + cl) * 64 + o) * PW + P] : 0.f;
    }
    __syncthreads();
    #pragma unroll
    for (int i = 0; i < 4; i++) {
        int Pl = ty + i * 8;
        int P  = P0 + Pl;
        if (P < PW) {
            float v = t[tx][Pl];
            __nv_bfloat16 h = __float2bfloat16(v);
            __nv_bfloat16 l = __float2bfloat16(v - __bfloat162float(h));
            size_t di = ((size_t)P * 64 + o) * 64 + (c0 + tx);
            g_Whi[di] = h;
            g_Wlo[di] = l;
        }
    }
}

// ============================================================
// Prepass 2: x [b*64+c][s=1024] fp32 -> Xhi/Xlo [s][b*64+c] bf16
// ============================================================
__global__ __launch_bounds__(256) void prep_x(const float* __restrict__ x) {
    __shared__ float t[32][33];
    const int s0  = blockIdx.x * 32;
    const int bc0 = blockIdx.y * 32;
    const int tx = threadIdx.x, ty = threadIdx.y;  // 32 x 8
    #pragma unroll
    for (int i = 0; i < 4; i++) {
        int bcl = ty + i * 8;
        t[bcl][tx] = x[(size_t)(bc0 + bcl) * 1024 + (s0 + tx)];
    }
    __syncthreads();
    #pragma unroll
    for (int i = 0; i < 4; i++) {
        int sl = ty + i * 8;
        float v = t[tx][sl];
        __nv_bfloat16 h = __float2bfloat16(v);
        __nv_bfloat16 l = __float2bfloat16(v - __bfloat162float(h));
        size_t di = (size_t)(s0 + sl) * 8192 + (bc0 + tx);
        g_Xhi[di] = h;
        g_Xlo[di] = l;
    }
}

// ============================================================
// Main kernel: 450 CTAs (2 positions each), 256 threads (4x2 warps).
// Per chunk (p, r): A = Xsplit[s(p,r)] 128x64 bf16 hi/lo (32KB),
//                   W = Wsplit[pos*9+r] 64x64 hi/lo (16KB).
// 2-stage cp.async pipeline; warp tile 32x32; 3-split mma.sync bf16.
// ============================================================
#define CHUNK_BYTES 49152           // 16K Ahi + 16K Alo + 8K Whi + 8K Wlo
#define SM_TOTAL    (2 * CHUNK_BYTES)

__device__ __forceinline__ void load_chunk(uint32_t dst, int pos0, int t, int tid) {
    const int p   = (t >= 9) ? 1 : 0;
    const int r   = t - p * 9;
    const int pos = pos0 + p;
    const int oi  = pos / 30;
    const int oj  = pos - oi * 30;
    const int s   = (oi + r / 3) * 32 + (oj + r % 3);
    const int P   = pos * 9 + r;
    const char* aH = (const char*)(g_Xhi + (size_t)s * 8192);
    const char* aL = (const char*)(g_Xlo + (size_t)s * 8192);
    const char* wH = (const char*)(g_Whi + (size_t)P * 4096);
    const char* wL = (const char*)(g_Wlo + (size_t)P * 4096);
    #pragma unroll
    for (int i = 0; i < 4; i++) {
        uint32_t off = (uint32_t)(tid + i * 256) * 16;
        uint32_t so  = SWZ(off);
        cp16(dst + so,         aH + off);
        cp16(dst + 16384 + so, aL + off);
    }
    #pragma unroll
    for (int i = 0; i < 2; i++) {
        uint32_t off = (uint32_t)(tid + i * 256) * 16;
        uint32_t so  = SWZ(off);
        cp16(dst + 32768 + so, wH + off);
        cp16(dst + 40960 + so, wL + off);
    }
}

__device__ __forceinline__ void compute_chunk(
    uint32_t base, float (&acc)[2][4][4],
    const uint32_t a_row[2], uint32_t a_cs, uint32_t a_xm,
    const uint32_t b_row[2], uint32_t b_cs, uint32_t b_xm)
{
    #pragma unroll
    for (int kk = 0; kk < 4; kk++) {
        const uint32_t acol = ((uint32_t)(kk * 32) + a_cs) ^ a_xm;
        const uint32_t bcol = ((uint32_t)(kk * 32) + b_cs) ^ b_xm;
        uint32_t Ah[2][4], Al[2][4], Bh[2][4], Bl[2][4];
        #pragma unroll
        for (int mt = 0; mt < 2; mt++) {
            ldsm_x4(Ah[mt], base         + a_row[mt] + acol);
            ldsm_x4(Al[mt], base + 16384 + a_row[mt] + acol);
        }
        #pragma unroll
        for (int np = 0; np < 2; np++) {
            ldsm_x4(Bh[np], base + 32768 + b_row[np] + bcol);
            ldsm_x4(Bl[np], base + 40960 + b_row[np] + bcol);
        }
        #pragma unroll
        for (int mt = 0; mt < 2; mt++)
            #pragma unroll
            for (int nt = 0; nt < 4; nt++) {
                const uint32_t* bh = &Bh[nt >> 1][(nt & 1) * 2];
                const uint32_t* bl = &Bl[nt >> 1][(nt & 1) * 2];
                mma_bf16(acc[mt][nt], Ah[mt], bh);
                mma_bf16(acc[mt][nt], Ah[mt], bl);
                mma_bf16(acc[mt][nt], Al[mt], bh);
            }
    }
}

__global__ __launch_bounds__(256, 1) void lc_main(const float* __restrict__ bias,
                                                  float* __restrict__ out) {
    extern __shared__ __align__(1024) char smem[];
    const uint32_t sb = smem_to_u32(smem);
    const int tid  = threadIdx.x;
    const int lane = tid & 31;
    const int warp = tid >> 5;
    const int wm   = warp & 3;    // 4 warps along M (batch)
    const int wn   = warp >> 2;   // 2 warps along N (out-ch)
    const int pos0 = blockIdx.x * 2;

    // ldmatrix lane address components (byte offsets within region)
    const int rowA = lane & 15;
    const uint32_t a_cs = (uint32_t)(lane >> 4) * 16;
    const uint32_t a_xm = (uint32_t)(rowA & 7) << 4;
    uint32_t a_row[2];
    #pragma unroll
    for (int mt = 0; mt < 2; mt++)
        a_row[mt] = (uint32_t)(wm * 32 + mt * 16 + rowA) * 128;

    const int rowB = (lane & 7) + ((lane >> 4) << 3);
    const uint32_t b_cs = (uint32_t)((lane >> 3) & 1) * 16;
    const uint32_t b_xm = (uint32_t)(lane & 7) << 4;
    uint32_t b_row[2];
    #pragma unroll
    for (int np = 0; np < 2; np++)
        b_row[np] = (uint32_t)(wn * 32 + np * 16 + rowB) * 128;

    float acc[2][2][4][4];
    #pragma unroll
    for (int p = 0; p < 2; p++)
        #pragma unroll
        for (int mt = 0; mt < 2; mt++)
            #pragma unroll
            for (int nt = 0; nt < 4; nt++)
                #pragma unroll
                for (int e = 0; e < 4; e++) acc[p][mt][nt][e] = 0.f;

    // 2-stage pipeline over 18 chunks
    load_chunk(sb, pos0, 0, tid);
    CP_COMMIT();

    int t = 0;
    #pragma unroll
    for (int p = 0; p < 2; p++) {
        for (int r = 0; r < 9; r++, t++) {
            if (t < 17) {
                load_chunk(sb + (uint32_t)((t + 1) & 1) * CHUNK_BYTES, pos0, t + 1, tid);
                CP_COMMIT();
                CP_WAIT(1);
            } else {
                CP_WAIT(0);
            }
            __syncthreads();
            compute_chunk(sb + (uint32_t)(t & 1) * CHUNK_BYTES, acc[p],
                          a_row, a_cs, a_xm, b_row, b_cs, b_xm);
            __syncthreads();
        }
    }

    // ---- epilogue: bias + float2 stores over the position pair ----
    #pragma unroll
    for (int mt = 0; mt < 2; mt++)
        #pragma unroll
        for (int nt = 0; nt < 4; nt++)
            #pragma unroll
            for (int half = 0; half < 2; half++) {
                const int b = wm * 32 + mt * 16 + (lane >> 2) + half * 8;
                #pragma unroll
                for (int cc = 0; cc < 2; cc++) {
                    const int o = wn * 32 + nt * 8 + (lane & 3) * 2 + cc;
                    const float2 bv = *(const float2*)(bias + (size_t)o * NPOS + pos0);
                    float2 v;
                    v.x = acc[0][mt][nt][half * 2 + cc] + bv.x;
                    v.y = acc[1][mt][nt][half * 2 + cc] + bv.y;
                    *(float2*)(out + ((size_t)b * 64 + o) * NPOS + pos0) = v;
                }
            }
}

// ============================================================
extern "C" void kernel_launch(void* const* d_in, const int* in_sizes, int n_in,
                              void* d_out, int out_size) {
    const float* x    = (const float*)d_in[0];   // [128,64,32,32]
    const float* wt   = (const float*)d_in[1];   // [64,64,30,30,3,3]
    const float* bias = (const float*)d_in[2];   // [64,30,30]
    float* out = (float*)d_out;                  // [128,64,30,30]

    cudaFuncSetAttribute(lc_main, cudaFuncAttributeMaxDynamicSharedMemorySize, SM_TOTAL);

    prep_w<<<dim3(254, 64, 2), dim3(32, 8)>>>(wt);
    prep_x<<<dim3(32, 256), dim3(32, 8)>>>(x);
    lc_main<<<NPOS / 2, 256, SM_TOTAL>>>(bias, out);
}

// round 5
// speedup vs baseline: 3.9681x; 1.1472x over previous
#include <cuda_runtime.h>
#include <cuda_bf16.h>
#include <cstdint>

// ============================================================
// LocallyConnectedLayer: out[b,o,i,j] = sum_{c,kh,kw} x[b,c,i+kh,j+kw]
//                        * weight[c,o,i,j,kh,kw] + bias[o,i,j]
// B=128, C=64, O=64, H=W=32, OH=OW=30, K=3.
// 900 independent GEMMs M=128,N=64,K=576.
// mma.sync.m16n8k16.bf16 with 3-product hi/lo split.
// R5: prepasses emit PRE-SWIZZLED (SW128) bf16 slices; lc_main loads them
// with cp.async.bulk (4-6 ops/step instead of 3072 cp.async) and dedups
// the A slices shared between the two positions of a CTA (18 -> 12 loads).
// ============================================================

#define NPOS 900
#define PW   8100      // NPOS*9

// ---- scratch (__device__ globals; allocation APIs are forbidden) ----
// All slices stored PRE-SWIZZLED with SW128 so lc_main can bulk-copy them.
__device__ __align__(1024) __nv_bfloat16 g_Whi[(size_t)PW * 64 * 64];   // [P]: 8KB slice [o][c]
__device__ __align__(1024) __nv_bfloat16 g_Wlo[(size_t)PW * 64 * 64];
__device__ __align__(1024) __nv_bfloat16 g_Xhi[(size_t)1024 * 8192];    // [s]: 16KB slice [b*64+c]
__device__ __align__(1024) __nv_bfloat16 g_Xlo[(size_t)1024 * 8192];

// ---- helpers ----
__device__ __forceinline__ uint32_t smem_to_u32(const void* p) {
    uint32_t a;
    asm("{ .reg .u64 t; cvta.to.shared.u64 t, %1; cvt.u32.u64 %0, t; }" : "=r"(a) : "l"(p));
    return a;
}
#define SWZ(off) ((off) ^ (((off) >> 3) & 0x70))

__device__ __forceinline__ void ldsm_x4(uint32_t a[4], uint32_t addr) {
    asm volatile("ldmatrix.sync.aligned.m8n8.x4.shared.b16 {%0,%1,%2,%3}, [%4];"
        : "=r"(a[0]), "=r"(a[1]), "=r"(a[2]), "=r"(a[3]) : "r"(addr));
}
__device__ __forceinline__ void mma_bf16(float c[4], const uint32_t a[4], const uint32_t b[2]) {
    asm volatile(
        "mma.sync.aligned.m16n8k16.row.col.f32.bf16.bf16.f32 "
        "{%0,%1,%2,%3},{%4,%5,%6,%7},{%8,%9},{%0,%1,%2,%3};"
        : "+f"(c[0]), "+f"(c[1]), "+f"(c[2]), "+f"(c[3])
        : "r"(a[0]), "r"(a[1]), "r"(a[2]), "r"(a[3]), "r"(b[0]), "r"(b[1]));
}
#define MBARRIER_INIT(mbar, count) \
    asm volatile("mbarrier.init.shared.b64 [%0], %1;" :: "r"((uint32_t)(mbar)), "r"((uint32_t)(count)) : "memory")
#define MBARRIER_EXPECT_TX(mbar, tx) \
    asm volatile("mbarrier.arrive.expect_tx.shared.b64 _, [%0], %1;" :: "r"((uint32_t)(mbar)), "r"((uint32_t)(tx)) : "memory")
#define MBARRIER_WAIT_PARITY(mbar, parity) do { \
    uint32_t _m = (uint32_t)(mbar); uint32_t _p = (uint32_t)(parity); uint32_t _d; \
    asm volatile("{\n\t.reg .pred p;\n\tmbarrier.try_wait.parity.acquire.cta.shared::cta.b64 p, [%1], %2;\n\tselp.b32 %0, 1, 0, p;\n\t}" \
        : "=r"(_d) : "r"(_m), "r"(_p) : "memory"); \
    if (!_d) { \
        asm volatile("{\n\t.reg .pred P1;\n\tWL_%=:\n\tmbarrier.try_wait.parity.acquire.cta.shared::cta.b64 P1, [%0], %1, 0x989680;\n\t@P1 bra.uni WD_%=;\n\tbra.uni WL_%=;\n\tWD_%=:\n\t}" \
            :: "r"(_m), "r"(_p) : "memory"); \
    } } while (0)
// 1D bulk async copy global->shared with mbarrier completion (SASS: UBLKCP)
__device__ __forceinline__ void bulk_g2s(uint32_t dst, const void* src, uint32_t bytes, uint32_t mbar) {
    asm volatile(
        "cp.async.bulk.shared::cluster.global.mbarrier::complete_tx::bytes [%0], [%1], %2, [%3];"
        :: "r"(dst), "l"(src), "r"(bytes), "r"(mbar) : "memory");
}

__device__ __forceinline__ uint32_t pack_bf162(float v0, float v1) {
    __nv_bfloat16 h0 = __float2bfloat16(v0), h1 = __float2bfloat16(v1);
    return (uint32_t)__bfloat16_as_ushort(h0) | ((uint32_t)__bfloat16_as_ushort(h1) << 16);
}

// ============================================================
// Prepass 1: weight [c][o][P] fp32 -> Whi/Wlo, slice P = [o][c] bf16,
// stored PRE-SWIZZLED. Block: 32 P x 64 c, one o. float4 loads, bf16x2 stores.
// ============================================================
__global__ __launch_bounds__(256) void prep_w(const float* __restrict__ wt) {
    __shared__ float t[64][33];
    const int P0  = blockIdx.x * 32;
    const int o   = blockIdx.y;
    const int tid = threadIdx.x;
    // phase 1: load 64 c-rows x 32 P (contiguous along P) as float4
    #pragma unroll
    for (int k = 0; k < 2; k++) {
        int idx = tid + k * 256;       // 0..511
        int c   = idx >> 3;            // 0..63
        int q   = idx & 7;             // float4 slot
        int P   = P0 + q * 4;
        const float* src = wt + (size_t)(c * 64 + o) * PW + P;
        float4 v;
        if (P + 3 < PW) v = *(const float4*)src;
        else {
            v.x = (P     < PW) ? src[0] : 0.f;
            v.y = (P + 1 < PW) ? src[1] : 0.f;
            v.z = (P + 2 < PW) ? src[2] : 0.f;
            v.w = (P + 3 < PW) ? src[3] : 0.f;
        }
        t[c][q * 4 + 0] = v.x; t[c][q * 4 + 1] = v.y;
        t[c][q * 4 + 2] = v.z; t[c][q * 4 + 3] = v.w;
    }
    __syncthreads();
    // phase 2: 32 P-rows x 32 c-pairs -> packed bf16x2, swizzled offsets
    #pragma unroll
    for (int k = 0; k < 4; k++) {
        int idx = tid + k * 256;       // 0..1023
        int pl  = idx >> 5;            // P row 0..31
        int px  = idx & 31;            // c-pair 0..31
        int P   = P0 + pl;
        if (P < PW) {
            float v0 = t[px * 2][pl], v1 = t[px * 2 + 1][pl];
            float h0f = __bfloat162float(__float2bfloat16(v0));
            float h1f = __bfloat162float(__float2bfloat16(v1));
            uint32_t hi = pack_bf162(v0, v1);
            uint32_t lo = pack_bf162(v0 - h0f, v1 - h1f);
            uint32_t off = SWZ((uint32_t)(o * 128 + px * 4));
            *(uint32_t*)((char*)g_Whi + (size_t)P * 8192 + off) = hi;
            *(uint32_t*)((char*)g_Wlo + (size_t)P * 8192 + off) = lo;
        }
    }
}

// ============================================================
// Prepass 2: x [bc=8192][s=1024] fp32 -> Xhi/Xlo, slice s = [bc] bf16,
// stored PRE-SWIZZLED. Block: 32 s x 64 bc.
// ============================================================
__global__ __launch_bounds__(256) void prep_x(const float* __restrict__ x) {
    __shared__ float t[64][33];
    const int s0  = blockIdx.x * 32;
    const int bc0 = blockIdx.y * 64;
    const int tid = threadIdx.x;
    #pragma unroll
    for (int k = 0; k < 2; k++) {
        int idx = tid + k * 256;
        int r   = idx >> 3;            // bc local 0..63
        int q   = idx & 7;
        float4 v = *(const float4*)(x + (size_t)(bc0 + r) * 1024 + s0 + q * 4);
        t[r][q * 4 + 0] = v.x; t[r][q * 4 + 1] = v.y;
        t[r][q * 4 + 2] = v.z; t[r][q * 4 + 3] = v.w;
    }
    __syncthreads();
    #pragma unroll
    for (int k = 0; k < 4; k++) {
        int idx = tid + k * 256;
        int sl  = idx >> 5;            // s row 0..31
        int px  = idx & 31;            // bc-pair within 64
        float v0 = t[px * 2][sl], v1 = t[px * 2 + 1][sl];
        float h0f = __bfloat162float(__float2bfloat16(v0));
        float h1f = __bfloat162float(__float2bfloat16(v1));
        uint32_t hi = pack_bf162(v0, v1);
        uint32_t lo = pack_bf162(v0 - h0f, v1 - h1f);
        uint32_t off = SWZ((uint32_t)(bc0 * 2 + px * 4));
        *(uint32_t*)((char*)g_Xhi + (size_t)(s0 + sl) * 16384 + off) = hi;
        *(uint32_t*)((char*)g_Xlo + (size_t)(s0 + sl) * 16384 + off) = lo;
    }
}

// ============================================================
// Main kernel: 450 CTAs (2 adjacent positions), 256 threads (4x2 warps).
// 12 slice-steps (kh 0..2 x jw 0..3): A slice (i+kh, j+jw) loaded ONCE,
// serves pos0 (kw=jw, if jw<3) and pos1 (kw=jw-1, if jw>0).
// Stage = A hi/lo 32KB + up to 2 W-pairs 16KB each = 64KB; 3-stage ring.
// Loads via cp.async.bulk + mbarrier expect_tx (single-thread issue).
// ============================================================
#define STAGE 65536u
#define SM_TOTAL (3 * 65536)

struct IssueCtx { uint32_t sb, mb; int pos0, oi, oj; };

__device__ __forceinline__ void issue_step(const IssueCtx& cx, int t2) {
    const int kh = t2 >> 2, jw = t2 & 3;
    const int s  = (cx.oi + kh) * 32 + cx.oj + jw;
    const int b  = t2 % 3;
    const uint32_t dst  = cx.sb + (uint32_t)b * STAGE;
    const uint32_t mbar = cx.mb + (uint32_t)b * 8;
    const int npair = ((jw > 0) && (jw < 3)) ? 2 : 1;
    MBARRIER_EXPECT_TX(mbar, 32768u + (uint32_t)npair * 16384u);
    bulk_g2s(dst,          (const char*)g_Xhi + (size_t)s * 16384, 16384u, mbar);
    bulk_g2s(dst + 16384u, (const char*)g_Xlo + (size_t)s * 16384, 16384u, mbar);
    uint32_t wdst = dst + 32768u;
    if (jw < 3) {
        size_t P = (size_t)(cx.pos0 * 9 + kh * 3 + jw);
        bulk_g2s(wdst,         (const char*)g_Whi + P * 8192, 8192u, mbar);
        bulk_g2s(wdst + 8192u, (const char*)g_Wlo + P * 8192, 8192u, mbar);
        wdst += 16384u;
    }
    if (jw > 0) {
        size_t P = (size_t)((cx.pos0 + 1) * 9 + kh * 3 + jw - 1);
        bulk_g2s(wdst,         (const char*)g_Whi + P * 8192, 8192u, mbar);
        bulk_g2s(wdst + 8192u, (const char*)g_Wlo + P * 8192, 8192u, mbar);
    }
}

__device__ __forceinline__ void comp_pair(
    uint32_t wbase, float (&acc)[2][4][4],
    const uint32_t (&Ah)[2][4], const uint32_t (&Al)[2][4],
    const uint32_t b_row[2], uint32_t bcol)
{
    uint32_t Bh[2][4], Bl[2][4];
    #pragma unroll
    for (int np = 0; np < 2; np++) {
        ldsm_x4(Bh[np], wbase + b_row[np] + bcol);
        ldsm_x4(Bl[np], wbase + 8192u + b_row[np] + bcol);
    }
    #pragma unroll
    for (int mt = 0; mt < 2; mt++)
        #pragma unroll
        for (int nt = 0; nt < 4; nt++) {
            const uint32_t* bh = &Bh[nt >> 1][(nt & 1) * 2];
            const uint32_t* bl = &Bl[nt >> 1][(nt & 1) * 2];
            mma_bf16(acc[mt][nt], Ah[mt], bh);
            mma_bf16(acc[mt][nt], Ah[mt], bl);
            mma_bf16(acc[mt][nt], Al[mt], bh);
        }
}

__global__ __launch_bounds__(256, 1) void lc_main(const float* __restrict__ bias,
                                                  float* __restrict__ out) {
    extern __shared__ __align__(1024) char smem[];
    __shared__ __align__(8) uint64_t mbar_s[3];
    const uint32_t sb = smem_to_u32(smem);
    const uint32_t mb = smem_to_u32(mbar_s);
    const int tid  = threadIdx.x;
    const int lane = tid & 31;
    const int warp = tid >> 5;
    const int wm   = warp & 3;    // 4 warps along M (batch)
    const int wn   = warp >> 2;   // 2 warps along N (out-ch)
    const int pos0 = blockIdx.x * 2;
    IssueCtx cx{sb, mb, pos0, pos0 / 30, pos0 % 30};

    if (tid == 0) {
        MBARRIER_INIT(mb, 1); MBARRIER_INIT(mb + 8, 1); MBARRIER_INIT(mb + 16, 1);
    }
    __syncthreads();

    // ldmatrix lane address components
    const int rowA = lane & 15;
    const uint32_t a_cs = (uint32_t)(lane >> 4) * 16;
    const uint32_t a_xm = (uint32_t)(rowA & 7) << 4;
    uint32_t a_row[2];
    #pragma unroll
    for (int mt = 0; mt < 2; mt++)
        a_row[mt] = (uint32_t)(wm * 32 + mt * 16 + rowA) * 128;

    const int rowB = (lane & 7) + ((lane >> 4) << 3);
    const uint32_t b_cs = (uint32_t)((lane >> 3) & 1) * 16;
    const uint32_t b_xm = (uint32_t)(lane & 7) << 4;
    uint32_t b_row[2];
    #pragma unroll
    for (int np = 0; np < 2; np++)
        b_row[np] = (uint32_t)(wn * 32 + np * 16 + rowB) * 128;

    float acc[2][2][4][4];
    #pragma unroll
    for (int p = 0; p < 2; p++)
        #pragma unroll
        for (int mt = 0; mt < 2; mt++)
            #pragma unroll
            for (int nt = 0; nt < 4; nt++)
                #pragma unroll
                for (int e = 0; e < 4; e++) acc[p][mt][nt][e] = 0.f;

    if (tid == 0) { issue_step(cx, 0); issue_step(cx, 1); }

    uint32_t ph = 0;
    for (int t = 0; t < 12; t++) {
        __syncthreads();                         // compute(t-1) done -> buf (t+2)%3 free
        if (tid == 0 && t < 10) issue_step(cx, t + 2);
        const int b = t % 3;
        const uint32_t pb = (ph >> b) & 1u;
        ph ^= 1u << b;
        MBARRIER_WAIT_PARITY(mb + (uint32_t)b * 8, pb);
        const uint32_t base = sb + (uint32_t)b * STAGE;
        const int jw = t & 3;
        const uint32_t w1off = (jw < 3) ? 16384u : 0u;   // slot of pair1
        #pragma unroll
        for (int kk = 0; kk < 4; kk++) {
            const uint32_t acol = ((uint32_t)(kk * 32) + a_cs) ^ a_xm;
            const uint32_t bcol = ((uint32_t)(kk * 32) + b_cs) ^ b_xm;
            uint32_t Ah[2][4], Al[2][4];
            #pragma unroll
            for (int mt = 0; mt < 2; mt++) {
                ldsm_x4(Ah[mt], base          + a_row[mt] + acol);
                ldsm_x4(Al[mt], base + 16384u + a_row[mt] + acol);
            }
            if (jw < 3) comp_pair(base + 32768u,         acc[0], Ah, Al, b_row, bcol);
            if (jw > 0) comp_pair(base + 32768u + w1off, acc[1], Ah, Al, b_row, bcol);
        }
    }

    // ---- epilogue: bias + float2 stores over the position pair ----
    #pragma unroll
    for (int mt = 0; mt < 2; mt++)
        #pragma unroll
        for (int nt = 0; nt < 4; nt++)
            #pragma unroll
            for (int half = 0; half < 2; half++) {
                const int b = wm * 32 + mt * 16 + (lane >> 2) + half * 8;
                #pragma unroll
                for (int cc = 0; cc < 2; cc++) {
                    const int o = wn * 32 + nt * 8 + (lane & 3) * 2 + cc;
                    const float2 bv = *(const float2*)(bias + (size_t)o * NPOS + pos0);
                    float2 v;
                    v.x = acc[0][mt][nt][half * 2 + cc] + bv.x;
                    v.y = acc[1][mt][nt][half * 2 + cc] + bv.y;
                    *(float2*)(out + ((size_t)b * 64 + o) * NPOS + pos0) = v;
                }
            }
}

// ============================================================
extern "C" void kernel_launch(void* const* d_in, const int* in_sizes, int n_in,
                              void* d_out, int out_size) {
    const float* x    = (const float*)d_in[0];   // [128,64,32,32]
    const float* wt   = (const float*)d_in[1];   // [64,64,30,30,3,3]
    const float* bias = (const float*)d_in[2];   // [64,30,30]
    float* out = (float*)d_out;                  // [128,64,30,30]

    cudaFuncSetAttribute(lc_main, cudaFuncAttributeMaxDynamicSharedMemorySize, SM_TOTAL);

    prep_w<<<dim3(254, 64), 256>>>(wt);
    prep_x<<<dim3(32, 128), 256>>>(x);
    lc_main<<<NPOS / 2, 256, SM_TOTAL>>>(bias, out);
}

// round 6
// speedup vs baseline: 4.2243x; 1.0646x over previous
#include <cuda_runtime.h>
#include <cuda_bf16.h>
#include <cstdint>

// ============================================================
// LocallyConnectedLayer: out[b,o,i,j] = sum_{c,kh,kw} x[b,c,i+kh,j+kw]
//                        * weight[c,o,i,j,kh,kw] + bias[o,i,j]
// B=128, C=64, O=64, H=W=32, OH=OW=30, K=3.
// mma.sync.m16n8k16.bf16 with 3-product hi/lo split.
// R6: split A-ring (2x32KB) / W-ring (2x16KB) -> 96KB smem -> 2 CTAs/SM;
//     prep stores vectorized to uint4; preps fused into one launch.
// ============================================================

#define NPOS 900
#define PW   8100      // NPOS*9

// ---- scratch (pre-swizzled SW128 bf16 slices) ----
__device__ __align__(1024) __nv_bfloat16 g_Whi[(size_t)PW * 64 * 64];   // [P]: 8KB slice [o][c]
__device__ __align__(1024) __nv_bfloat16 g_Wlo[(size_t)PW * 64 * 64];
__device__ __align__(1024) __nv_bfloat16 g_Xhi[(size_t)1024 * 8192];    // [s]: 16KB slice [b*64+c]
__device__ __align__(1024) __nv_bfloat16 g_Xlo[(size_t)1024 * 8192];

// ---- helpers ----
__device__ __forceinline__ uint32_t smem_to_u32(const void* p) {
    uint32_t a;
    asm("{ .reg .u64 t; cvta.to.shared.u64 t, %1; cvt.u32.u64 %0, t; }" : "=r"(a) : "l"(p));
    return a;
}
#define SWZ(off) ((off) ^ (((off) >> 3) & 0x70))

__device__ __forceinline__ void ldsm_x4(uint32_t a[4], uint32_t addr) {
    asm volatile("ldmatrix.sync.aligned.m8n8.x4.shared.b16 {%0,%1,%2,%3}, [%4];"
        : "=r"(a[0]), "=r"(a[1]), "=r"(a[2]), "=r"(a[3]) : "r"(addr));
}
__device__ __forceinline__ void mma_bf16(float c[4], const uint32_t a[4], const uint32_t b[2]) {
    asm volatile(
        "mma.sync.aligned.m16n8k16.row.col.f32.bf16.bf16.f32 "
        "{%0,%1,%2,%3},{%4,%5,%6,%7},{%8,%9},{%0,%1,%2,%3};"
        : "+f"(c[0]), "+f"(c[1]), "+f"(c[2]), "+f"(c[3])
        : "r"(a[0]), "r"(a[1]), "r"(a[2]), "r"(a[3]), "r"(b[0]), "r"(b[1]));
}
#define MBARRIER_INIT(mbar, count) \
    asm volatile("mbarrier.init.shared.b64 [%0], %1;" :: "r"((uint32_t)(mbar)), "r"((uint32_t)(count)) : "memory")
#define MBARRIER_EXPECT_TX(mbar, tx) \
    asm volatile("mbarrier.arrive.expect_tx.shared.b64 _, [%0], %1;" :: "r"((uint32_t)(mbar)), "r"((uint32_t)(tx)) : "memory")
#define MBARRIER_WAIT_PARITY(mbar, parity) do { \
    uint32_t _m = (uint32_t)(mbar); uint32_t _p = (uint32_t)(parity); uint32_t _d; \
    asm volatile("{\n\t.reg .pred p;\n\tmbarrier.try_wait.parity.acquire.cta.shared::cta.b64 p, [%1], %2;\n\tselp.b32 %0, 1, 0, p;\n\t}" \
        : "=r"(_d) : "r"(_m), "r"(_p) : "memory"); \
    if (!_d) { \
        asm volatile("{\n\t.reg .pred P1;\n\tWL_%=:\n\tmbarrier.try_wait.parity.acquire.cta.shared::cta.b64 P1, [%0], %1, 0x989680;\n\t@P1 bra.uni WD_%=;\n\tbra.uni WL_%=;\n\tWD_%=:\n\t}" \
            :: "r"(_m), "r"(_p) : "memory"); \
    } } while (0)
__device__ __forceinline__ void bulk_g2s(uint32_t dst, const void* src, uint32_t bytes, uint32_t mbar) {
    asm volatile(
        "cp.async.bulk.shared::cluster.global.mbarrier::complete_tx::bytes [%0], [%1], %2, [%3];"
        :: "r"(dst), "l"(src), "r"(bytes), "r"(mbar) : "memory");
}
__device__ __forceinline__ uint32_t pack_bf162(float v0, float v1) {
    __nv_bfloat16 h0 = __float2bfloat16(v0), h1 = __float2bfloat16(v1);
    return (uint32_t)__bfloat16_as_ushort(h0) | ((uint32_t)__bfloat16_as_ushort(h1) << 16);
}
// split helper: hi = bf16(v), lo = bf16(v - hi)
__device__ __forceinline__ void split2(float v0, float v1, uint32_t& hi, uint32_t& lo) {
    float h0 = __bfloat162float(__float2bfloat16(v0));
    float h1 = __bfloat162float(__float2bfloat16(v1));
    hi = pack_bf162(v0, v1);
    lo = pack_bf162(v0 - h0, v1 - h1);
}

// ============================================================
// Fused prepass: blocks [0, 16256) do weight, [16256, 20352) do x.
// Both: float4 gmem loads, smem transpose, uint4 pre-swizzled stores.
// ============================================================
#define NWBLK 16256   // 254 P-tiles x 64 o
__global__ __launch_bounds__(256) void prep_all(const float* __restrict__ wt,
                                                const float* __restrict__ x) {
    __shared__ float t[64][33];
    const int tid = threadIdx.x;
    if (blockIdx.x < NWBLK) {
        // ---- weight path: tile = 32 P x 64 c for one o ----
        const int P0 = (blockIdx.x % 254) * 32;
        const int o  = blockIdx.x / 254;
        #pragma unroll
        for (int k = 0; k < 2; k++) {
            int idx = tid + k * 256;   // 0..511
            int c   = idx >> 3;        // 0..63
            int q   = idx & 7;
            int P   = P0 + q * 4;
            const float* src = wt + (size_t)(c * 64 + o) * PW + P;
            float4 v;
            if (P + 3 < PW) v = *(const float4*)src;
            else {
                v.x = (P     < PW) ? src[0] : 0.f;
                v.y = (P + 1 < PW) ? src[1] : 0.f;
                v.z = (P + 2 < PW) ? src[2] : 0.f;
                v.w = (P + 3 < PW) ? src[3] : 0.f;
            }
            t[c][q * 4 + 0] = v.x; t[c][q * 4 + 1] = v.y;
            t[c][q * 4 + 2] = v.z; t[c][q * 4 + 3] = v.w;
        }
        __syncthreads();
        // stores: each thread packs 8 c-values -> one uint4 hi + one uint4 lo
        {
            int pl = tid >> 3;         // P row 0..31
            int q8 = tid & 7;          // 8-channel group
            int P  = P0 + pl;
            if (P < PW) {
                uint32_t hi[4], lo[4];
                #pragma unroll
                for (int j = 0; j < 4; j++)
                    split2(t[q8 * 8 + j * 2][pl], t[q8 * 8 + j * 2 + 1][pl], hi[j], lo[j]);
                uint32_t off = SWZ((uint32_t)(o * 128 + q8 * 16));
                *(uint4*)((char*)g_Whi + (size_t)P * 8192 + off) = *(uint4*)hi;
                *(uint4*)((char*)g_Wlo + (size_t)P * 8192 + off) = *(uint4*)lo;
            }
        }
    } else {
        // ---- x path: tile = 32 s x 64 bc ----
        const int i   = blockIdx.x - NWBLK;   // 0..4095
        const int s0  = (i & 31) * 32;
        const int bc0 = (i >> 5) * 64;
        #pragma unroll
        for (int k = 0; k < 2; k++) {
            int idx = tid + k * 256;
            int r   = idx >> 3;
            int q   = idx & 7;
            float4 v = *(const float4*)(x + (size_t)(bc0 + r) * 1024 + s0 + q * 4);
            t[r][q * 4 + 0] = v.x; t[r][q * 4 + 1] = v.y;
            t[r][q * 4 + 2] = v.z; t[r][q * 4 + 3] = v.w;
        }
        __syncthreads();
        {
            int sl = tid >> 3;
            int q8 = tid & 7;
            uint32_t hi[4], lo[4];
            #pragma unroll
            for (int j = 0; j < 4; j++)
                split2(t[q8 * 8 + j * 2][sl], t[q8 * 8 + j * 2 + 1][sl], hi[j], lo[j]);
            uint32_t off = SWZ((uint32_t)(bc0 * 2 + q8 * 16));
            *(uint4*)((char*)g_Xhi + (size_t)(s0 + sl) * 16384 + off) = *(uint4*)hi;
            *(uint4*)((char*)g_Xlo + (size_t)(s0 + sl) * 16384 + off) = *(uint4*)lo;
        }
    }
}

// ============================================================
// Main kernel: 450 CTAs (2 adjacent positions), 256 threads (4x2 warps).
// 12 A slice-groups g=(kh,jw) in a 2x32KB ring; 18 W-pair steps in a
// 2x16KB ring. Step order per kh: (pi,r-off) = (0,0)(0,1)(1,0)(0,2)(1,1)(1,2).
// 96KB smem total -> 2 CTAs/SM.
// ============================================================
#define A_STAGE 32768u
#define W_STAGE 16384u
#define SM_TOTAL (2 * 32768 + 2 * 16384)   // 98304

struct Ctx { uint32_t sb, mb; int pos0, oi, oj; };

__device__ __forceinline__ void issueA(const Ctx& cx, int g) {
    const int s = (cx.oi + (g >> 2)) * 32 + cx.oj + (g & 3);
    const uint32_t dst  = cx.sb + (uint32_t)(g & 1) * A_STAGE;
    const uint32_t mbar = cx.mb + (uint32_t)(g & 1) * 8;
    MBARRIER_EXPECT_TX(mbar, 32768u);
    bulk_g2s(dst,          (const char*)g_Xhi + (size_t)s * 16384, 16384u, mbar);
    bulk_g2s(dst + 16384u, (const char*)g_Xlo + (size_t)s * 16384, 16384u, mbar);
}
__device__ __forceinline__ void issueW(const Ctx& cx, int w) {
    const int kh = (w >= 12) ? 2 : (w >= 6 ? 1 : 0);
    const int u  = w - kh * 6;
    const int pi = (0x34 >> u) & 1;
    const int r  = kh * 3 + ((0x984 >> (2 * u)) & 3);
    const size_t P = (size_t)((cx.pos0 + pi) * 9 + r);
    const uint32_t dst  = cx.sb + 2 * A_STAGE + (uint32_t)(w & 1) * W_STAGE;
    const uint32_t mbar = cx.mb + 16 + (uint32_t)(w & 1) * 8;
    MBARRIER_EXPECT_TX(mbar, 16384u);
    bulk_g2s(dst,         (const char*)g_Whi + P * 8192, 8192u, mbar);
    bulk_g2s(dst + 8192u, (const char*)g_Wlo + P * 8192, 8192u, mbar);
}

__device__ __forceinline__ void step_compute(
    uint32_t abase, uint32_t wbase, float (&acc)[2][4][4],
    const uint32_t a_row[2], uint32_t a_cs, uint32_t a_xm,
    const uint32_t b_row[2], uint32_t b_cs, uint32_t b_xm)
{
    #pragma unroll
    for (int kk = 0; kk < 4; kk++) {
        const uint32_t acol = ((uint32_t)(kk * 32) + a_cs) ^ a_xm;
        const uint32_t bcol = ((uint32_t)(kk * 32) + b_cs) ^ b_xm;
        uint32_t Ah[2][4], Al[2][4], Bh[2][4], Bl[2][4];
        #pragma unroll
        for (int mt = 0; mt < 2; mt++) {
            ldsm_x4(Ah[mt], abase          + a_row[mt] + acol);
            ldsm_x4(Al[mt], abase + 16384u + a_row[mt] + acol);
        }
        #pragma unroll
        for (int np = 0; np < 2; np++) {
            ldsm_x4(Bh[np], wbase         + b_row[np] + bcol);
            ldsm_x4(Bl[np], wbase + 8192u + b_row[np] + bcol);
        }
        #pragma unroll
        for (int mt = 0; mt < 2; mt++)
            #pragma unroll
            for (int nt = 0; nt < 4; nt++) {
                const uint32_t* bh = &Bh[nt >> 1][(nt & 1) * 2];
                const uint32_t* bl = &Bl[nt >> 1][(nt & 1) * 2];
                mma_bf16(acc[mt][nt], Ah[mt], bh);
                mma_bf16(acc[mt][nt], Ah[mt], bl);
                mma_bf16(acc[mt][nt], Al[mt], bh);
            }
    }
}

__global__ __launch_bounds__(256, 2) void lc_main(const float* __restrict__ bias,
                                                  float* __restrict__ out) {
    extern __shared__ __align__(1024) char smem[];
    __shared__ __align__(8) uint64_t mbar_s[4];   // A0,A1,W0,W1
    const uint32_t sb = smem_to_u32(smem);
    const uint32_t mb = smem_to_u32(mbar_s);
    const int tid  = threadIdx.x;
    const int lane = tid & 31;
    const int warp = tid >> 5;
    const int wm   = warp & 3;
    const int wn   = warp >> 2;
    const int pos0 = blockIdx.x * 2;
    Ctx cx{sb, mb, pos0, pos0 / 30, pos0 % 30};

    if (tid == 0) {
        #pragma unroll
        for (int i = 0; i < 4; i++) MBARRIER_INIT(mb + i * 8, 1);
    }
    __syncthreads();

    const int rowA = lane & 15;
    const uint32_t a_cs = (uint32_t)(lane >> 4) * 16;
    const uint32_t a_xm = (uint32_t)(rowA & 7) << 4;
    uint32_t a_row[2];
    #pragma unroll
    for (int mt = 0; mt < 2; mt++)
        a_row[mt] = (uint32_t)(wm * 32 + mt * 16 + rowA) * 128;

    const int rowB = (lane & 7) + ((lane >> 4) << 3);
    const uint32_t b_cs = (uint32_t)((lane >> 3) & 1) * 16;
    const uint32_t b_xm = (uint32_t)(lane & 7) << 4;
    uint32_t b_row[2];
    #pragma unroll
    for (int np = 0; np < 2; np++)
        b_row[np] = (uint32_t)(wn * 32 + np * 16 + rowB) * 128;

    float acc0[2][4][4], acc1[2][4][4];
    #pragma unroll
    for (int mt = 0; mt < 2; mt++)
        #pragma unroll
        for (int nt = 0; nt < 4; nt++)
            #pragma unroll
            for (int e = 0; e < 4; e++) { acc0[mt][nt][e] = 0.f; acc1[mt][nt][e] = 0.f; }

    if (tid == 0) { issueA(cx, 0); issueA(cx, 1); issueW(cx, 0); issueW(cx, 1); }

    for (int w = 0; w < 18; w++) {
        const int kh = (w >= 12) ? 2 : (w >= 6 ? 1 : 0);
        const int u  = w - kh * 6;
        const int g  = kh * 4 + ((u + 1) >> 1);
        const int pi = (0x34 >> u) & 1;
        if ((0x2B >> u) & 1)                      // first step of A group g
            MBARRIER_WAIT_PARITY(mb + (uint32_t)(g & 1) * 8, (uint32_t)((g >> 1) & 1));
        MBARRIER_WAIT_PARITY(mb + 16 + (uint32_t)(w & 1) * 8, (uint32_t)((w >> 1) & 1));
        const uint32_t abase = sb + (uint32_t)(g & 1) * A_STAGE;
        const uint32_t wbase = sb + 2 * A_STAGE + (uint32_t)(w & 1) * W_STAGE;
        if (pi == 0) step_compute(abase, wbase, acc0, a_row, a_cs, a_xm, b_row, b_cs, b_xm);
        else         step_compute(abase, wbase, acc1, a_row, a_cs, a_xm, b_row, b_cs, b_xm);
        __syncthreads();
        if (tid == 0) {
            if (((0x35 >> u) & 1) && g + 2 < 12) issueA(cx, g + 2);  // last step of group
            if (w + 2 < 18) issueW(cx, w + 2);
        }
    }

    // ---- epilogue: bias + float2 stores over the position pair ----
    #pragma unroll
    for (int mt = 0; mt < 2; mt++)
        #pragma unroll
        for (int nt = 0; nt < 4; nt++)
            #pragma unroll
            for (int half = 0; half < 2; half++) {
                const int b = wm * 32 + mt * 16 + (lane >> 2) + half * 8;
                #pragma unroll
                for (int cc = 0; cc < 2; cc++) {
                    const int o = wn * 32 + nt * 8 + (lane & 3) * 2 + cc;
                    const float2 bv = *(const float2*)(bias + (size_t)o * NPOS + pos0);
                    float2 v;
                    v.x = acc0[mt][nt][half * 2 + cc] + bv.x;
                    v.y = acc1[mt][nt][half * 2 + cc] + bv.y;
                    *(float2*)(out + ((size_t)b * 64 + o) * NPOS + pos0) = v;
                }
            }
}

// ============================================================
extern "C" void kernel_launch(void* const* d_in, const int* in_sizes, int n_in,
                              void* d_out, int out_size) {
    const float* x    = (const float*)d_in[0];   // [128,64,32,32]
    const float* wt   = (const float*)d_in[1];   // [64,64,30,30,3,3]
    const float* bias = (const float*)d_in[2];   // [64,30,30]
    float* out = (float*)d_out;                  // [128,64,30,30]

    cudaFuncSetAttribute(lc_main, cudaFuncAttributeMaxDynamicSharedMemorySize, SM_TOTAL);

    prep_all<<<NWBLK + 4096, 256>>>(wt, x);
    lc_main<<<NPOS / 2, 256, SM_TOTAL>>>(bias, out);
}

// round 7
// speedup vs baseline: 4.6058x; 1.0903x over previous
#include <cuda_runtime.h>
#include <cuda_fp16.h>
#include <cstdint>

// ============================================================
// LocallyConnectedLayer: out[b,o,i,j] = sum_{c,kh,kw} x[b,c,i+kh,j+kw]
//                        * weight[c,o,i,j,kh,kw] + bias[o,i,j]
// B=128, C=64, O=64, H=W=32, OH=OW=30, K=3.
// R7: single-product fp16 HMMA (fp32 accum). Norm rel-err model ~3e-4 < 1e-3.
// Prepasses emit pre-swizzled fp16 slices; lc_main bulk-copies them,
// 12 slice-steps with A dedup between the CTA's two positions.
// ============================================================

#define NPOS 900
#define PW   8100      // NPOS*9

// ---- scratch (pre-swizzled SW128 fp16 slices) ----
__device__ __align__(1024) __half g_Wf[(size_t)PW * 64 * 64];   // [P]: 8KB slice [o][c]
__device__ __align__(1024) __half g_Xf[(size_t)1024 * 8192];    // [s]: 16KB slice [b*64+c]

// ---- helpers ----
__device__ __forceinline__ uint32_t smem_to_u32(const void* p) {
    uint32_t a;
    asm("{ .reg .u64 t; cvta.to.shared.u64 t, %1; cvt.u32.u64 %0, t; }" : "=r"(a) : "l"(p));
    return a;
}
#define SWZ(off) ((off) ^ (((off) >> 3) & 0x70))

__device__ __forceinline__ void ldsm_x4(uint32_t a[4], uint32_t addr) {
    asm volatile("ldmatrix.sync.aligned.m8n8.x4.shared.b16 {%0,%1,%2,%3}, [%4];"
        : "=r"(a[0]), "=r"(a[1]), "=r"(a[2]), "=r"(a[3]) : "r"(addr));
}
__device__ __forceinline__ void mma_f16(float c[4], const uint32_t a[4], const uint32_t b[2]) {
    asm volatile(
        "mma.sync.aligned.m16n8k16.row.col.f32.f16.f16.f32 "
        "{%0,%1,%2,%3},{%4,%5,%6,%7},{%8,%9},{%0,%1,%2,%3};"
        : "+f"(c[0]), "+f"(c[1]), "+f"(c[2]), "+f"(c[3])
        : "r"(a[0]), "r"(a[1]), "r"(a[2]), "r"(a[3]), "r"(b[0]), "r"(b[1]));
}
#define MBARRIER_INIT(mbar, count) \
    asm volatile("mbarrier.init.shared.b64 [%0], %1;" :: "r"((uint32_t)(mbar)), "r"((uint32_t)(count)) : "memory")
#define MBARRIER_EXPECT_TX(mbar, tx) \
    asm volatile("mbarrier.arrive.expect_tx.shared.b64 _, [%0], %1;" :: "r"((uint32_t)(mbar)), "r"((uint32_t)(tx)) : "memory")
#define MBARRIER_WAIT_PARITY(mbar, parity) do { \
    uint32_t _m = (uint32_t)(mbar); uint32_t _p = (uint32_t)(parity); uint32_t _d; \
    asm volatile("{\n\t.reg .pred p;\n\tmbarrier.try_wait.parity.acquire.cta.shared::cta.b64 p, [%1], %2;\n\tselp.b32 %0, 1, 0, p;\n\t}" \
        : "=r"(_d) : "r"(_m), "r"(_p) : "memory"); \
    if (!_d) { \
        asm volatile("{\n\t.reg .pred P1;\n\tWL_%=:\n\tmbarrier.try_wait.parity.acquire.cta.shared::cta.b64 P1, [%0], %1, 0x989680;\n\t@P1 bra.uni WD_%=;\n\tbra.uni WL_%=;\n\tWD_%=:\n\t}" \
            :: "r"(_m), "r"(_p) : "memory"); \
    } } while (0)
__device__ __forceinline__ void bulk_g2s(uint32_t dst, const void* src, uint32_t bytes, uint32_t mbar) {
    asm volatile(
        "cp.async.bulk.shared::cluster.global.mbarrier::complete_tx::bytes [%0], [%1], %2, [%3];"
        :: "r"(dst), "l"(src), "r"(bytes), "r"(mbar) : "memory");
}

// ============================================================
// Fused prepass: blocks [0, NWBLK) weight, [NWBLK, NWBLK+4096) x.
// float4 loads -> smem transpose -> uint4 fp16 pre-swizzled stores.
// ============================================================
#define NWBLK 16256   // 254 P-tiles x 64 o
__global__ __launch_bounds__(256) void prep_all(const float* __restrict__ wt,
                                                const float* __restrict__ x) {
    __shared__ float t[64][33];
    const int tid = threadIdx.x;
    if (blockIdx.x < NWBLK) {
        // ---- weight: tile = 32 P x 64 c for one o ----
        const int P0 = (blockIdx.x % 254) * 32;
        const int o  = blockIdx.x / 254;
        #pragma unroll
        for (int k = 0; k < 2; k++) {
            int idx = tid + k * 256;
            int c   = idx >> 3;
            int q   = idx & 7;
            int P   = P0 + q * 4;
            const float* src = wt + (size_t)(c * 64 + o) * PW + P;
            float4 v;
            if (P + 3 < PW) v = *(const float4*)src;
            else {
                v.x = (P     < PW) ? src[0] : 0.f;
                v.y = (P + 1 < PW) ? src[1] : 0.f;
                v.z = (P + 2 < PW) ? src[2] : 0.f;
                v.w = (P + 3 < PW) ? src[3] : 0.f;
            }
            t[c][q * 4 + 0] = v.x; t[c][q * 4 + 1] = v.y;
            t[c][q * 4 + 2] = v.z; t[c][q * 4 + 3] = v.w;
        }
        __syncthreads();
        {
            int pl = tid >> 3;   // P row 0..31
            int q8 = tid & 7;    // 8-channel group
            int P  = P0 + pl;
            if (P < PW) {
                uint32_t pk[4];
                #pragma unroll
                for (int j = 0; j < 4; j++) {
                    __half2 h = __floats2half2_rn(t[q8 * 8 + j * 2][pl], t[q8 * 8 + j * 2 + 1][pl]);
                    pk[j] = *(uint32_t*)&h;
                }
                uint32_t off = SWZ((uint32_t)(o * 128 + q8 * 16));
                *(uint4*)((char*)g_Wf + (size_t)P * 8192 + off) = *(uint4*)pk;
            }
        }
    } else {
        // ---- x: tile = 32 s x 64 bc ----
        const int i   = blockIdx.x - NWBLK;
        const int s0  = (i & 31) * 32;
        const int bc0 = (i >> 5) * 64;
        #pragma unroll
        for (int k = 0; k < 2; k++) {
            int idx = tid + k * 256;
            int r   = idx >> 3;
            int q   = idx & 7;
            float4 v = *(const float4*)(x + (size_t)(bc0 + r) * 1024 + s0 + q * 4);
            t[r][q * 4 + 0] = v.x; t[r][q * 4 + 1] = v.y;
            t[r][q * 4 + 2] = v.z; t[r][q * 4 + 3] = v.w;
        }
        __syncthreads();
        {
            int sl = tid >> 3;
            int q8 = tid & 7;
            uint32_t pk[4];
            #pragma unroll
            for (int j = 0; j < 4; j++) {
                __half2 h = __floats2half2_rn(t[q8 * 8 + j * 2][sl], t[q8 * 8 + j * 2 + 1][sl]);
                pk[j] = *(uint32_t*)&h;
            }
            uint32_t off = SWZ((uint32_t)(bc0 * 2 + q8 * 16));
            *(uint4*)((char*)g_Xf + (size_t)(s0 + sl) * 16384 + off) = *(uint4*)pk;
        }
    }
}

// ============================================================
// Main: 450 CTAs (2 adjacent positions), 256 threads (4x2 warps).
// 12 slice-steps (kh 0..2 x jw 0..3): A slice (i+kh, j+jw) loaded once,
// serves pos0 (kw=jw, jw<3) and pos1 (kw=jw-1, jw>0).
// Stage = A 16KB + up to 2 W 8KB = 32KB; 3-stage ring = 96KB -> 2 CTAs/SM.
// ============================================================
#define STAGE 32768u
#define SM_TOTAL (3 * 32768)

struct Ctx { uint32_t sb, mb; int pos0, oi, oj; };

__device__ __forceinline__ void issue_step(const Ctx& cx, int t2) {
    const int kh = t2 >> 2, jw = t2 & 3;
    const int s  = (cx.oi + kh) * 32 + cx.oj + jw;
    const int b  = t2 % 3;
    const uint32_t dst  = cx.sb + (uint32_t)b * STAGE;
    const uint32_t mbar = cx.mb + (uint32_t)b * 8;
    const int npair = ((jw > 0) && (jw < 3)) ? 2 : 1;
    MBARRIER_EXPECT_TX(mbar, 16384u + (uint32_t)npair * 8192u);
    bulk_g2s(dst, (const char*)g_Xf + (size_t)s * 16384, 16384u, mbar);
    uint32_t wdst = dst + 16384u;
    if (jw < 3) {
        size_t P = (size_t)(cx.pos0 * 9 + kh * 3 + jw);
        bulk_g2s(wdst, (const char*)g_Wf + P * 8192, 8192u, mbar);
        wdst += 8192u;
    }
    if (jw > 0) {
        size_t P = (size_t)((cx.pos0 + 1) * 9 + kh * 3 + jw - 1);
        bulk_g2s(wdst, (const char*)g_Wf + P * 8192, 8192u, mbar);
    }
}

__device__ __forceinline__ void comp_pair(
    uint32_t wbase, float (&acc)[2][4][4],
    const uint32_t (&A)[2][4], const uint32_t b_row[2], uint32_t bcol)
{
    uint32_t Bm[2][4];
    #pragma unroll
    for (int np = 0; np < 2; np++)
        ldsm_x4(Bm[np], wbase + b_row[np] + bcol);
    #pragma unroll
    for (int mt = 0; mt < 2; mt++)
        #pragma unroll
        for (int nt = 0; nt < 4; nt++)
            mma_f16(acc[mt][nt], A[mt], &Bm[nt >> 1][(nt & 1) * 2]);
}

__global__ __launch_bounds__(256, 2) void lc_main(const float* __restrict__ bias,
                                                  float* __restrict__ out) {
    extern __shared__ __align__(1024) char smem[];
    __shared__ __align__(8) uint64_t mbar_s[3];
    const uint32_t sb = smem_to_u32(smem);
    const uint32_t mb = smem_to_u32(mbar_s);
    const int tid  = threadIdx.x;
    const int lane = tid & 31;
    const int warp = tid >> 5;
    const int wm   = warp & 3;    // 4 warps along M (batch)
    const int wn   = warp >> 2;   // 2 warps along N (out-ch)
    const int pos0 = blockIdx.x * 2;
    Ctx cx{sb, mb, pos0, pos0 / 30, pos0 % 30};

    if (tid == 0) {
        MBARRIER_INIT(mb, 1); MBARRIER_INIT(mb + 8, 1); MBARRIER_INIT(mb + 16, 1);
    }
    __syncthreads();

    const int rowA = lane & 15;
    const uint32_t a_cs = (uint32_t)(lane >> 4) * 16;
    const uint32_t a_xm = (uint32_t)(rowA & 7) << 4;
    uint32_t a_row[2];
    #pragma unroll
    for (int mt = 0; mt < 2; mt++)
        a_row[mt] = (uint32_t)(wm * 32 + mt * 16 + rowA) * 128;

    const int rowB = (lane & 7) + ((lane >> 4) << 3);
    const uint32_t b_cs = (uint32_t)((lane >> 3) & 1) * 16;
    const uint32_t b_xm = (uint32_t)(lane & 7) << 4;
    uint32_t b_row[2];
    #pragma unroll
    for (int np = 0; np < 2; np++)
        b_row[np] = (uint32_t)(wn * 32 + np * 16 + rowB) * 128;

    float acc[2][2][4][4];
    #pragma unroll
    for (int p = 0; p < 2; p++)
        #pragma unroll
        for (int mt = 0; mt < 2; mt++)
            #pragma unroll
            for (int nt = 0; nt < 4; nt++)
                #pragma unroll
                for (int e = 0; e < 4; e++) acc[p][mt][nt][e] = 0.f;

    if (tid == 0) { issue_step(cx, 0); issue_step(cx, 1); }

    uint32_t ph = 0;
    for (int t = 0; t < 12; t++) {
        __syncthreads();                    // compute(t-1) done -> buf (t+2)%3 free
        if (tid == 0 && t < 10) issue_step(cx, t + 2);
        const int b = t % 3;
        const uint32_t pb = (ph >> b) & 1u;
        ph ^= 1u << b;
        MBARRIER_WAIT_PARITY(mb + (uint32_t)b * 8, pb);
        const uint32_t base = sb + (uint32_t)b * STAGE;
        const int jw = t & 3;
        const uint32_t w1off = (jw < 3) ? 8192u : 0u;
        #pragma unroll
        for (int kk = 0; kk < 4; kk++) {
            const uint32_t acol = ((uint32_t)(kk * 32) + a_cs) ^ a_xm;
            const uint32_t bcol = ((uint32_t)(kk * 32) + b_cs) ^ b_xm;
            uint32_t A[2][4];
            #pragma unroll
            for (int mt = 0; mt < 2; mt++)
                ldsm_x4(A[mt], base + a_row[mt] + acol);
            if (jw < 3) comp_pair(base + 16384u,         acc[0], A, b_row, bcol);
            if (jw > 0) comp_pair(base + 16384u + w1off, acc[1], A, b_row, bcol);
        }
    }

    // ---- epilogue: bias + float2 stores over the position pair ----
    #pragma unroll
    for (int mt = 0; mt < 2; mt++)
        #pragma unroll
        for (int nt = 0; nt < 4; nt++)
            #pragma unroll
            for (int half = 0; half < 2; half++) {
                const int b = wm * 32 + mt * 16 + (lane >> 2) + half * 8;
                #pragma unroll
                for (int cc = 0; cc < 2; cc++) {
                    const int o = wn * 32 + nt * 8 + (lane & 3) * 2 + cc;
                    const float2 bv = *(const float2*)(bias + (size_t)o * NPOS + pos0);
                    float2 v;
                    v.x = acc[0][mt][nt][half * 2 + cc] + bv.x;
                    v.y = acc[1][mt][nt][half * 2 + cc] + bv.y;
                    *(float2*)(out + ((size_t)b * 64 + o) * NPOS + pos0) = v;
                }
            }
}

// ============================================================
extern "C" void kernel_launch(void* const* d_in, const int* in_sizes, int n_in,
                              void* d_out, int out_size) {
    const float* x    = (const float*)d_in[0];   // [128,64,32,32]
    const float* wt   = (const float*)d_in[1];   // [64,64,30,30,3,3]
    const float* bias = (const float*)d_in[2];   // [64,30,30]
    float* out = (float*)d_out;                  // [128,64,30,30]

    cudaFuncSetAttribute(lc_main, cudaFuncAttributeMaxDynamicSharedMemorySize, SM_TOTAL);

    prep_all<<<NWBLK + 4096, 256>>>(wt, x);
    lc_main<<<NPOS / 2, 256, SM_TOTAL>>>(bias, out);
}

// round 8
// speedup vs baseline: 5.1481x; 1.1177x over previous
#include <cuda_runtime.h>
#include <cuda_fp16.h>
#include <cstdint>

// ============================================================
// LocallyConnectedLayer: out[b,o,i,j] = sum_{c,kh,kw} x[b,c,i+kh,j+kw]
//                        * weight[c,o,i,j,kh,kw] + bias[o,i,j]
// B=128, C=64, O=64, H=W=32, OH=OW=30, K=3.
// R8: single-product fp16 HMMA. 1 position/CTA -> 32-reg acc -> 3 CTAs/SM,
// 900 CTAs = 2.03 clean waves. Prep uses 64x64 tiles (2x ILP).
// ============================================================

#define NPOS 900
#define PW   8100      // NPOS*9

// ---- scratch (pre-swizzled SW128 fp16 slices) ----
__device__ __align__(1024) __half g_Wf[(size_t)PW * 64 * 64];   // [P]: 8KB slice [o][c]
__device__ __align__(1024) __half g_Xf[(size_t)1024 * 8192];    // [s]: 16KB slice [b*64+c]

// ---- helpers ----
__device__ __forceinline__ uint32_t smem_to_u32(const void* p) {
    uint32_t a;
    asm("{ .reg .u64 t; cvta.to.shared.u64 t, %1; cvt.u32.u64 %0, t; }" : "=r"(a) : "l"(p));
    return a;
}
#define SWZ(off) ((off) ^ (((off) >> 3) & 0x70))

__device__ __forceinline__ void ldsm_x4(uint32_t a[4], uint32_t addr) {
    asm volatile("ldmatrix.sync.aligned.m8n8.x4.shared.b16 {%0,%1,%2,%3}, [%4];"
        : "=r"(a[0]), "=r"(a[1]), "=r"(a[2]), "=r"(a[3]) : "r"(addr));
}
__device__ __forceinline__ void mma_f16(float c[4], const uint32_t a[4], const uint32_t b[2]) {
    asm volatile(
        "mma.sync.aligned.m16n8k16.row.col.f32.f16.f16.f32 "
        "{%0,%1,%2,%3},{%4,%5,%6,%7},{%8,%9},{%0,%1,%2,%3};"
        : "+f"(c[0]), "+f"(c[1]), "+f"(c[2]), "+f"(c[3])
        : "r"(a[0]), "r"(a[1]), "r"(a[2]), "r"(a[3]), "r"(b[0]), "r"(b[1]));
}
#define MBARRIER_INIT(mbar, count) \
    asm volatile("mbarrier.init.shared.b64 [%0], %1;" :: "r"((uint32_t)(mbar)), "r"((uint32_t)(count)) : "memory")
#define MBARRIER_EXPECT_TX(mbar, tx) \
    asm volatile("mbarrier.arrive.expect_tx.shared.b64 _, [%0], %1;" :: "r"((uint32_t)(mbar)), "r"((uint32_t)(tx)) : "memory")
#define MBARRIER_WAIT_PARITY(mbar, parity) do { \
    uint32_t _m = (uint32_t)(mbar); uint32_t _p = (uint32_t)(parity); uint32_t _d; \
    asm volatile("{\n\t.reg .pred p;\n\tmbarrier.try_wait.parity.acquire.cta.shared::cta.b64 p, [%1], %2;\n\tselp.b32 %0, 1, 0, p;\n\t}" \
        : "=r"(_d) : "r"(_m), "r"(_p) : "memory"); \
    if (!_d) { \
        asm volatile("{\n\t.reg .pred P1;\n\tWL_%=:\n\tmbarrier.try_wait.parity.acquire.cta.shared::cta.b64 P1, [%0], %1, 0x989680;\n\t@P1 bra.uni WD_%=;\n\tbra.uni WL_%=;\n\tWD_%=:\n\t}" \
            :: "r"(_m), "r"(_p) : "memory"); \
    } } while (0)
__device__ __forceinline__ void bulk_g2s(uint32_t dst, const void* src, uint32_t bytes, uint32_t mbar) {
    asm volatile(
        "cp.async.bulk.shared::cluster.global.mbarrier::complete_tx::bytes [%0], [%1], %2, [%3];"
        :: "r"(dst), "l"(src), "r"(bytes), "r"(mbar) : "memory");
}

// ============================================================
// Fused prepass, 64x64 tiles.
// Blocks [0, NWBLK): weight (127 P-tiles x 64 o); [NWBLK, +2048): x.
// float4 loads -> smem transpose -> uint4 fp16 pre-swizzled stores.
// ============================================================
#define NWBLK 8128   // 127 * 64
__global__ __launch_bounds__(256) void prep_all(const float* __restrict__ wt,
                                                const float* __restrict__ x) {
    __shared__ float t[64][65];
    const int tid = threadIdx.x;
    if (blockIdx.x < NWBLK) {
        // ---- weight: tile = 64 P x 64 c for one o ----
        const int P0 = (blockIdx.x % 127) * 64;
        const int o  = blockIdx.x / 127;
        #pragma unroll
        for (int k = 0; k < 4; k++) {
            int idx = tid + k * 256;   // 0..1023
            int c   = idx >> 4;        // 0..63
            int q   = idx & 15;
            int P   = P0 + q * 4;
            const float* src = wt + (size_t)(c * 64 + o) * PW + P;
            float4 v;
            if (P + 3 < PW) v = *(const float4*)src;
            else {
                v.x = (P     < PW) ? src[0] : 0.f;
                v.y = (P + 1 < PW) ? src[1] : 0.f;
                v.z = (P + 2 < PW) ? src[2] : 0.f;
                v.w = (P + 3 < PW) ? src[3] : 0.f;
            }
            t[c][q * 4 + 0] = v.x; t[c][q * 4 + 1] = v.y;
            t[c][q * 4 + 2] = v.z; t[c][q * 4 + 3] = v.w;
        }
        __syncthreads();
        #pragma unroll
        for (int k = 0; k < 2; k++) {
            int idx = tid + k * 256;   // 0..511
            int pl  = idx >> 3;        // P row 0..63
            int q8  = idx & 7;         // 8-channel group
            int P   = P0 + pl;
            if (P < PW) {
                uint32_t pk[4];
                #pragma unroll
                for (int j = 0; j < 4; j++) {
                    __half2 h = __floats2half2_rn(t[q8 * 8 + j * 2][pl], t[q8 * 8 + j * 2 + 1][pl]);
                    pk[j] = *(uint32_t*)&h;
                }
                uint32_t off = SWZ((uint32_t)(o * 128 + q8 * 16));
                *(uint4*)((char*)g_Wf + (size_t)P * 8192 + off) = *(uint4*)pk;
            }
        }
    } else {
        // ---- x: tile = 64 s x 64 bc ----
        const int i   = blockIdx.x - NWBLK;   // 0..2047
        const int s0  = (i & 15) * 64;
        const int bc0 = (i >> 4) * 64;
        #pragma unroll
        for (int k = 0; k < 4; k++) {
            int idx = tid + k * 256;
            int r   = idx >> 4;        // bc local 0..63
            int q   = idx & 15;
            float4 v = *(const float4*)(x + (size_t)(bc0 + r) * 1024 + s0 + q * 4);
            t[r][q * 4 + 0] = v.x; t[r][q * 4 + 1] = v.y;
            t[r][q * 4 + 2] = v.z; t[r][q * 4 + 3] = v.w;
        }
        __syncthreads();
        #pragma unroll
        for (int k = 0; k < 2; k++) {
            int idx = tid + k * 256;
            int sl  = idx >> 3;        // s row 0..63
            int q8  = idx & 7;
            uint32_t pk[4];
            #pragma unroll
            for (int j = 0; j < 4; j++) {
                __half2 h = __floats2half2_rn(t[q8 * 8 + j * 2][sl], t[q8 * 8 + j * 2 + 1][sl]);
                pk[j] = *(uint32_t*)&h;
            }
            uint32_t off = SWZ((uint32_t)(bc0 * 2 + q8 * 16));
            *(uint4*)((char*)g_Xf + (size_t)(s0 + sl) * 16384 + off) = *(uint4*)pk;
        }
    }
}

// ============================================================
// Main: 900 CTAs (1 position each), 256 threads (4x2 warps, warp tile 32x32).
// 9 steps (r = kh*3+kw): stage = A 16KB + W 8KB = 24KB; 3-stage ring = 72KB
// -> 3 CTAs/SM (reg budget 84 via launch_bounds).
// ============================================================
#define STAGE 24576u
#define SM_TOTAL (3 * 24576)

__device__ __forceinline__ void issue_step(uint32_t sb, uint32_t mb, int pos,
                                           int oi, int oj, int r) {
    const int s = (oi + r / 3) * 32 + (oj + r % 3);
    const int b = r % 3;
    const uint32_t dst  = sb + (uint32_t)b * STAGE;
    const uint32_t mbar = mb + (uint32_t)b * 8;
    MBARRIER_EXPECT_TX(mbar, 24576u);
    bulk_g2s(dst,          (const char*)g_Xf + (size_t)s * 16384, 16384u, mbar);
    bulk_g2s(dst + 16384u, (const char*)g_Wf + (size_t)(pos * 9 + r) * 8192, 8192u, mbar);
}

__global__ __launch_bounds__(256, 3) void lc_main(const float* __restrict__ bias,
                                                  float* __restrict__ out) {
    extern __shared__ __align__(1024) char smem[];
    __shared__ __align__(8) uint64_t mbar_s[3];
    const uint32_t sb = smem_to_u32(smem);
    const uint32_t mb = smem_to_u32(mbar_s);
    const int tid  = threadIdx.x;
    const int lane = tid & 31;
    const int warp = tid >> 5;
    const int wm   = warp & 3;    // 4 warps along M (batch)
    const int wn   = warp >> 2;   // 2 warps along N (out-ch)
    const int pos  = blockIdx.x;
    const int oi   = pos / 30;
    const int oj   = pos % 30;

    if (tid == 0) {
        MBARRIER_INIT(mb, 1); MBARRIER_INIT(mb + 8, 1); MBARRIER_INIT(mb + 16, 1);
    }
    __syncthreads();

    const int rowA = lane & 15;
    const uint32_t a_cs = (uint32_t)(lane >> 4) * 16;
    const uint32_t a_xm = (uint32_t)(rowA & 7) << 4;
    uint32_t a_row[2];
    #pragma unroll
    for (int mt = 0; mt < 2; mt++)
        a_row[mt] = (uint32_t)(wm * 32 + mt * 16 + rowA) * 128;

    const int rowB = (lane & 7) + ((lane >> 4) << 3);
    const uint32_t b_cs = (uint32_t)((lane >> 3) & 1) * 16;
    const uint32_t b_xm = (uint32_t)(lane & 7) << 4;
    uint32_t b_row[2];
    #pragma unroll
    for (int np = 0; np < 2; np++)
        b_row[np] = (uint32_t)(wn * 32 + np * 16 + rowB) * 128;

    float acc[2][4][4];
    #pragma unroll
    for (int mt = 0; mt < 2; mt++)
        #pragma unroll
        for (int nt = 0; nt < 4; nt++)
            #pragma unroll
            for (int e = 0; e < 4; e++) acc[mt][nt][e] = 0.f;

    if (tid == 0) {
        issue_step(sb, mb, pos, oi, oj, 0);
        issue_step(sb, mb, pos, oi, oj, 1);
        issue_step(sb, mb, pos, oi, oj, 2);
    }

    uint32_t ph = 0;
    for (int r = 0; r < 9; r++) {
        const int b = r % 3;
        const uint32_t pb = (ph >> b) & 1u;
        ph ^= 1u << b;
        MBARRIER_WAIT_PARITY(mb + (uint32_t)b * 8, pb);
        const uint32_t abase = sb + (uint32_t)b * STAGE;
        const uint32_t wbase = abase + 16384u;
        #pragma unroll
        for (int kk = 0; kk < 4; kk++) {
            const uint32_t acol = ((uint32_t)(kk * 32) + a_cs) ^ a_xm;
            const uint32_t bcol = ((uint32_t)(kk * 32) + b_cs) ^ b_xm;
            uint32_t A[2][4], Bm[2][4];
            #pragma unroll
            for (int mt = 0; mt < 2; mt++)
                ldsm_x4(A[mt], abase + a_row[mt] + acol);
            #pragma unroll
            for (int np = 0; np < 2; np++)
                ldsm_x4(Bm[np], wbase + b_row[np] + bcol);
            #pragma unroll
            for (int mt = 0; mt < 2; mt++)
                #pragma unroll
                for (int nt = 0; nt < 4; nt++)
                    mma_f16(acc[mt][nt], A[mt], &Bm[nt >> 1][(nt & 1) * 2]);
        }
        __syncthreads();
        if (tid == 0 && r + 3 < 9) issue_step(sb, mb, pos, oi, oj, r + 3);
    }

    // ---- epilogue: bias + scalar stores (adjacent-pos CTAs merge in L2) ----
    float bv[4][2];
    #pragma unroll
    for (int nt = 0; nt < 4; nt++)
        #pragma unroll
        for (int cc = 0; cc < 2; cc++)
            bv[nt][cc] = bias[(size_t)(wn * 32 + nt * 8 + (lane & 3) * 2 + cc) * NPOS + pos];
    #pragma unroll
    for (int mt = 0; mt < 2; mt++)
        #pragma unroll
        for (int half = 0; half < 2; half++) {
            const int b = wm * 32 + mt * 16 + (lane >> 2) + half * 8;
            #pragma unroll
            for (int nt = 0; nt < 4; nt++)
                #pragma unroll
                for (int cc = 0; cc < 2; cc++) {
                    const int o = wn * 32 + nt * 8 + (lane & 3) * 2 + cc;
                    out[((size_t)b * 64 + o) * NPOS + pos] =
                        acc[mt][nt][half * 2 + cc] + bv[nt][cc];
                }
        }
}

// ============================================================
extern "C" void kernel_launch(void* const* d_in, const int* in_sizes, int n_in,
                              void* d_out, int out_size) {
    const float* x    = (const float*)d_in[0];   // [128,64,32,32]
    const float* wt   = (const float*)d_in[1];   // [64,64,30,30,3,3]
    const float* bias = (const float*)d_in[2];   // [64,30,30]
    float* out = (float*)d_out;                  // [128,64,30,30]

    cudaFuncSetAttribute(lc_main, cudaFuncAttributeMaxDynamicSharedMemorySize, SM_TOTAL);

    prep_all<<<NWBLK + 2048, 256>>>(wt, x);
    lc_main<<<NPOS, 256, SM_TOTAL>>>(bias, out);
}

// round 9
// speedup vs baseline: 6.5238x; 1.2672x over previous
#include <cuda_runtime.h>
#include <cuda_fp16.h>
#include <cstdint>

// ============================================================
// LocallyConnectedLayer: out[b,o,i,j] = sum_{c,kh,kw} x[b,c,i+kh,j+kw]
//                        * weight[c,o,i,j,kh,kw] + bias[o,i,j]
// B=128, C=64, O=64, H=W=32, OH=OW=30, K=3.
// R9: same fp16 HMMA mainloop as R8 (3 CTAs/SM), but epilogue stores to a
// [pos][b*64+o] scratch (sector-perfect, kills the 8x L2 store inflation),
// followed by a tiled transpose kernel into the final [b][o][pos] layout.
// ============================================================

#define NPOS 900
#define PW   8100      // NPOS*9

// ---- scratch (pre-swizzled SW128 fp16 slices + output staging) ----
__device__ __align__(1024) __half g_Wf[(size_t)PW * 64 * 64];   // [P]: 8KB slice [o][c]
__device__ __align__(1024) __half g_Xf[(size_t)1024 * 8192];    // [s]: 16KB slice [b*64+c]
__device__ __align__(1024) float  g_Y[(size_t)NPOS * 8192];     // [pos][b*64+o], bias included

// ---- helpers ----
__device__ __forceinline__ uint32_t smem_to_u32(const void* p) {
    uint32_t a;
    asm("{ .reg .u64 t; cvta.to.shared.u64 t, %1; cvt.u32.u64 %0, t; }" : "=r"(a) : "l"(p));
    return a;
}
#define SWZ(off) ((off) ^ (((off) >> 3) & 0x70))

__device__ __forceinline__ void ldsm_x4(uint32_t a[4], uint32_t addr) {
    asm volatile("ldmatrix.sync.aligned.m8n8.x4.shared.b16 {%0,%1,%2,%3}, [%4];"
        : "=r"(a[0]), "=r"(a[1]), "=r"(a[2]), "=r"(a[3]) : "r"(addr));
}
__device__ __forceinline__ void mma_f16(float c[4], const uint32_t a[4], const uint32_t b[2]) {
    asm volatile(
        "mma.sync.aligned.m16n8k16.row.col.f32.f16.f16.f32 "
        "{%0,%1,%2,%3},{%4,%5,%6,%7},{%8,%9},{%0,%1,%2,%3};"
        : "+f"(c[0]), "+f"(c[1]), "+f"(c[2]), "+f"(c[3])
        : "r"(a[0]), "r"(a[1]), "r"(a[2]), "r"(a[3]), "r"(b[0]), "r"(b[1]));
}
#define MBARRIER_INIT(mbar, count) \
    asm volatile("mbarrier.init.shared.b64 [%0], %1;" :: "r"((uint32_t)(mbar)), "r"((uint32_t)(count)) : "memory")
#define MBARRIER_EXPECT_TX(mbar, tx) \
    asm volatile("mbarrier.arrive.expect_tx.shared.b64 _, [%0], %1;" :: "r"((uint32_t)(mbar)), "r"((uint32_t)(tx)) : "memory")
#define MBARRIER_WAIT_PARITY(mbar, parity) do { \
    uint32_t _m = (uint32_t)(mbar); uint32_t _p = (uint32_t)(parity); uint32_t _d; \
    asm volatile("{\n\t.reg .pred p;\n\tmbarrier.try_wait.parity.acquire.cta.shared::cta.b64 p, [%1], %2;\n\tselp.b32 %0, 1, 0, p;\n\t}" \
        : "=r"(_d) : "r"(_m), "r"(_p) : "memory"); \
    if (!_d) { \
        asm volatile("{\n\t.reg .pred P1;\n\tWL_%=:\n\tmbarrier.try_wait.parity.acquire.cta.shared::cta.b64 P1, [%0], %1, 0x989680;\n\t@P1 bra.uni WD_%=;\n\tbra.uni WL_%=;\n\tWD_%=:\n\t}" \
            :: "r"(_m), "r"(_p) : "memory"); \
    } } while (0)
__device__ __forceinline__ void bulk_g2s(uint32_t dst, const void* src, uint32_t bytes, uint32_t mbar) {
    asm volatile(
        "cp.async.bulk.shared::cluster.global.mbarrier::complete_tx::bytes [%0], [%1], %2, [%3];"
        :: "r"(dst), "l"(src), "r"(bytes), "r"(mbar) : "memory");
}

// ============================================================
// Fused prepass, 64x64 tiles (unchanged from R8 — at DRAM roofline).
// ============================================================
#define NWBLK 8128   // 127 * 64
__global__ __launch_bounds__(256) void prep_all(const float* __restrict__ wt,
                                                const float* __restrict__ x) {
    __shared__ float t[64][65];
    const int tid = threadIdx.x;
    if (blockIdx.x < NWBLK) {
        const int P0 = (blockIdx.x % 127) * 64;
        const int o  = blockIdx.x / 127;
        #pragma unroll
        for (int k = 0; k < 4; k++) {
            int idx = tid + k * 256;
            int c   = idx >> 4;
            int q   = idx & 15;
            int P   = P0 + q * 4;
            const float* src = wt + (size_t)(c * 64 + o) * PW + P;
            float4 v;
            if (P + 3 < PW) v = *(const float4*)src;
            else {
                v.x = (P     < PW) ? src[0] : 0.f;
                v.y = (P + 1 < PW) ? src[1] : 0.f;
                v.z = (P + 2 < PW) ? src[2] : 0.f;
                v.w = (P + 3 < PW) ? src[3] : 0.f;
            }
            t[c][q * 4 + 0] = v.x; t[c][q * 4 + 1] = v.y;
            t[c][q * 4 + 2] = v.z; t[c][q * 4 + 3] = v.w;
        }
        __syncthreads();
        #pragma unroll
        for (int k = 0; k < 2; k++) {
            int idx = tid + k * 256;
            int pl  = idx >> 3;
            int q8  = idx & 7;
            int P   = P0 + pl;
            if (P < PW) {
                uint32_t pk[4];
                #pragma unroll
                for (int j = 0; j < 4; j++) {
                    __half2 h = __floats2half2_rn(t[q8 * 8 + j * 2][pl], t[q8 * 8 + j * 2 + 1][pl]);
                    pk[j] = *(uint32_t*)&h;
                }
                uint32_t off = SWZ((uint32_t)(o * 128 + q8 * 16));
                *(uint4*)((char*)g_Wf + (size_t)P * 8192 + off) = *(uint4*)pk;
            }
        }
    } else {
        const int i   = blockIdx.x - NWBLK;
        const int s0  = (i & 15) * 64;
        const int bc0 = (i >> 4) * 64;
        #pragma unroll
        for (int k = 0; k < 4; k++) {
            int idx = tid + k * 256;
            int r   = idx >> 4;
            int q   = idx & 15;
            float4 v = *(const float4*)(x + (size_t)(bc0 + r) * 1024 + s0 + q * 4);
            t[r][q * 4 + 0] = v.x; t[r][q * 4 + 1] = v.y;
            t[r][q * 4 + 2] = v.z; t[r][q * 4 + 3] = v.w;
        }
        __syncthreads();
        #pragma unroll
        for (int k = 0; k < 2; k++) {
            int idx = tid + k * 256;
            int sl  = idx >> 3;
            int q8  = idx & 7;
            uint32_t pk[4];
            #pragma unroll
            for (int j = 0; j < 4; j++) {
                __half2 h = __floats2half2_rn(t[q8 * 8 + j * 2][sl], t[q8 * 8 + j * 2 + 1][sl]);
                pk[j] = *(uint32_t*)&h;
            }
            uint32_t off = SWZ((uint32_t)(bc0 * 2 + q8 * 16));
            *(uint4*)((char*)g_Xf + (size_t)(s0 + sl) * 16384 + off) = *(uint4*)pk;
        }
    }
}

// ============================================================
// Main: 900 CTAs (1 position each), 256 threads (4x2 warps, warp tile 32x32).
// 9 steps; 3-stage 24KB ring = 72KB -> 3 CTAs/SM. Epilogue -> g_Y[pos][bo]
// with float2 stores that fill whole 32B sectors (4 lanes per sector).
// ============================================================
#define STAGE 24576u
#define SM_TOTAL (3 * 24576)

__device__ __forceinline__ void issue_step(uint32_t sb, uint32_t mb, int pos,
                                           int oi, int oj, int r) {
    const int s = (oi + r / 3) * 32 + (oj + r % 3);
    const int b = r % 3;
    const uint32_t dst  = sb + (uint32_t)b * STAGE;
    const uint32_t mbar = mb + (uint32_t)b * 8;
    MBARRIER_EXPECT_TX(mbar, 24576u);
    bulk_g2s(dst,          (const char*)g_Xf + (size_t)s * 16384, 16384u, mbar);
    bulk_g2s(dst + 16384u, (const char*)g_Wf + (size_t)(pos * 9 + r) * 8192, 8192u, mbar);
}

__global__ __launch_bounds__(256, 3) void lc_main(const float* __restrict__ bias) {
    extern __shared__ __align__(1024) char smem[];
    __shared__ __align__(8) uint64_t mbar_s[3];
    const uint32_t sb = smem_to_u32(smem);
    const uint32_t mb = smem_to_u32(mbar_s);
    const int tid  = threadIdx.x;
    const int lane = tid & 31;
    const int warp = tid >> 5;
    const int wm   = warp & 3;    // 4 warps along M (batch)
    const int wn   = warp >> 2;   // 2 warps along N (out-ch)
    const int pos  = blockIdx.x;
    const int oi   = pos / 30;
    const int oj   = pos % 30;

    if (tid == 0) {
        MBARRIER_INIT(mb, 1); MBARRIER_INIT(mb + 8, 1); MBARRIER_INIT(mb + 16, 1);
    }
    __syncthreads();

    const int rowA = lane & 15;
    const uint32_t a_cs = (uint32_t)(lane >> 4) * 16;
    const uint32_t a_xm = (uint32_t)(rowA & 7) << 4;
    uint32_t a_row[2];
    #pragma unroll
    for (int mt = 0; mt < 2; mt++)
        a_row[mt] = (uint32_t)(wm * 32 + mt * 16 + rowA) * 128;

    const int rowB = (lane & 7) + ((lane >> 4) << 3);
    const uint32_t b_cs = (uint32_t)((lane >> 3) & 1) * 16;
    const uint32_t b_xm = (uint32_t)(lane & 7) << 4;
    uint32_t b_row[2];
    #pragma unroll
    for (int np = 0; np < 2; np++)
        b_row[np] = (uint32_t)(wn * 32 + np * 16 + rowB) * 128;

    float acc[2][4][4];
    #pragma unroll
    for (int mt = 0; mt < 2; mt++)
        #pragma unroll
        for (int nt = 0; nt < 4; nt++)
            #pragma unroll
            for (int e = 0; e < 4; e++) acc[mt][nt][e] = 0.f;

    if (tid == 0) {
        issue_step(sb, mb, pos, oi, oj, 0);
        issue_step(sb, mb, pos, oi, oj, 1);
        issue_step(sb, mb, pos, oi, oj, 2);
    }

    uint32_t ph = 0;
    for (int r = 0; r < 9; r++) {
        const int b = r % 3;
        const uint32_t pb = (ph >> b) & 1u;
        ph ^= 1u << b;
        MBARRIER_WAIT_PARITY(mb + (uint32_t)b * 8, pb);
        const uint32_t abase = sb + (uint32_t)b * STAGE;
        const uint32_t wbase = abase + 16384u;
        #pragma unroll
        for (int kk = 0; kk < 4; kk++) {
            const uint32_t acol = ((uint32_t)(kk * 32) + a_cs) ^ a_xm;
            const uint32_t bcol = ((uint32_t)(kk * 32) + b_cs) ^ b_xm;
            uint32_t A[2][4], Bm[2][4];
            #pragma unroll
            for (int mt = 0; mt < 2; mt++)
                ldsm_x4(A[mt], abase + a_row[mt] + acol);
            #pragma unroll
            for (int np = 0; np < 2; np++)
                ldsm_x4(Bm[np], wbase + b_row[np] + bcol);
            #pragma unroll
            for (int mt = 0; mt < 2; mt++)
                #pragma unroll
                for (int nt = 0; nt < 4; nt++)
                    mma_f16(acc[mt][nt], A[mt], &Bm[nt >> 1][(nt & 1) * 2]);
        }
        __syncthreads();
        if (tid == 0 && r + 3 < 9) issue_step(sb, mb, pos, oi, oj, r + 3);
    }

    // ---- epilogue: bias + sector-perfect float2 stores to g_Y[pos][b*64+o] ----
    float bv[4][2];
    #pragma unroll
    for (int nt = 0; nt < 4; nt++)
        #pragma unroll
        for (int cc = 0; cc < 2; cc++)
            bv[nt][cc] = bias[(size_t)(wn * 32 + nt * 8 + (lane & 3) * 2 + cc) * NPOS + pos];
    float* yp = g_Y + (size_t)pos * 8192;
    #pragma unroll
    for (int mt = 0; mt < 2; mt++)
        #pragma unroll
        for (int half = 0; half < 2; half++) {
            const int b = wm * 32 + mt * 16 + (lane >> 2) + half * 8;
            #pragma unroll
            for (int nt = 0; nt < 4; nt++) {
                const int o0 = wn * 32 + nt * 8 + (lane & 3) * 2;
                float2 v;
                v.x = acc[mt][nt][half * 2 + 0] + bv[nt][0];
                v.y = acc[mt][nt][half * 2 + 1] + bv[nt][1];
                *(float2*)(yp + b * 64 + o0) = v;
            }
        }
}

// ============================================================
// Transpose: g_Y[pos][bo] -> out[bo][pos].  Tiles: 36 pos x 128 bo
// (900 = 25*36, 8192 = 64*128 — exact). 256 threads.
// ============================================================
__global__ __launch_bounds__(256) void lc_tr(float* __restrict__ out) {
    __shared__ float t[36][130];
    const int tid  = threadIdx.x;
    const int pos0 = blockIdx.x * 36;
    const int bo0  = blockIdx.y * 128;
    // phase 1: read 36 rows x 128 floats (float4 along bo, fully coalesced)
    #pragma unroll
    for (int k = 0; k < 5; k++) {
        int idx = tid + k * 256;           // 0..1151
        if (idx < 1152) {
            int p = idx >> 5, q = idx & 31;
            float4 v = *(const float4*)(g_Y + (size_t)(pos0 + p) * 8192 + bo0 + q * 4);
            t[p][q * 4 + 0] = v.x; t[p][q * 4 + 1] = v.y;
            t[p][q * 4 + 2] = v.z; t[p][q * 4 + 3] = v.w;
        }
    }
    __syncthreads();
    // phase 2: write 128 bo-rows x 9 float4 along pos (144B contiguous runs)
    #pragma unroll
    for (int k = 0; k < 5; k++) {
        int idx = tid + k * 256;           // 0..1151
        if (idx < 1152) {
            int f  = idx % 9;              // float4 slot along pos
            int bo = idx / 9;              // 0..127
            float4 v;
            v.x = t[f * 4 + 0][bo];
            v.y = t[f * 4 + 1][bo];
            v.z = t[f * 4 + 2][bo];
            v.w = t[f * 4 + 3][bo];
            *(float4*)(out + (size_t)(bo0 + bo) * NPOS + pos0 + f * 4) = v;
        }
    }
}

// ============================================================
extern "C" void kernel_launch(void* const* d_in, const int* in_sizes, int n_in,
                              void* d_out, int out_size) {
    const float* x    = (const float*)d_in[0];   // [128,64,32,32]
    const float* wt   = (const float*)d_in[1];   // [64,64,30,30,3,3]
    const float* bias = (const float*)d_in[2];   // [64,30,30]
    float* out = (float*)d_out;                  // [128,64,30,30]

    cudaFuncSetAttribute(lc_main, cudaFuncAttributeMaxDynamicSharedMemorySize, SM_TOTAL);

    prep_all<<<NWBLK + 2048, 256>>>(wt, x);
    lc_main<<<NPOS, 256, SM_TOTAL>>>(bias);
    lc_tr<<<dim3(25, 64), 256>>>(out);
}